// round 13
// baseline (speedup 1.0000x reference)
#include <cuda_runtime.h>
#include <cuda_bf16.h>
#include <cstdint>

#define NROWS 262144
#define HC 64
#define KOFF 27
#define TILE_M 128
#define NBLK (NROWS / TILE_M)

// weight fragments per layer: 27 k * 4 ks * 8 nt * 32 lanes uint4
#define WFRAG_PER_LAYER (KOFF * 4 * 8 * 32)

// ---------------- device scratch (no allocations allowed) ----------------
// Row NROWS is a zero sentinel (zero-initialized, never written) so gathers
// need no bounds check.
__device__ __align__(128) __nv_bfloat16 g_xh[(size_t)(NROWS + 8) * HC];
__device__ __align__(128) __nv_bfloat16 g_xl[(size_t)(NROWS + 8) * HC];
__device__ __align__(128) __nv_bfloat16 g_mh[(size_t)(NROWS + 8) * HC];
__device__ __align__(128) __nv_bfloat16 g_ml[(size_t)(NROWS + 8) * HC];
// W in mma-B fragment order: uint4 = {bh_r0, bh_r1, bl_r0, bl_r1}
__device__ uint4 g_wf[2 * WFRAG_PER_LAYER];

// ---------------- helpers (baseline PTX: ldmatrix / mma.sync) ------------
__device__ __forceinline__ uint32_t smem_u32(const void* p) {
    uint32_t a;
    asm("{ .reg .u64 t; cvta.to.shared.u64 t, %1; cvt.u32.u64 %0, t; }" : "=r"(a) : "l"(p));
    return a;
}
__device__ __forceinline__ void ldm4(uint32_t* r, uint32_t addr) {
    asm volatile("ldmatrix.sync.aligned.m8n8.x4.shared.b16 {%0,%1,%2,%3}, [%4];"
                 : "=r"(r[0]), "=r"(r[1]), "=r"(r[2]), "=r"(r[3]) : "r"(addr));
}
__device__ __forceinline__ void mma16816(float* c, const uint32_t* a, const uint32_t* b) {
    asm volatile("mma.sync.aligned.m16n8k16.row.col.f32.bf16.bf16.f32 "
                 "{%0,%1,%2,%3}, {%4,%5,%6,%7}, {%8,%9}, {%0,%1,%2,%3};"
                 : "+f"(c[0]), "+f"(c[1]), "+f"(c[2]), "+f"(c[3])
                 : "r"(a[0]), "r"(a[1]), "r"(a[2]), "r"(a[3]), "r"(b[0]), "r"(b[1]));
}
__device__ __forceinline__ void split1(float v, __nv_bfloat16& h, __nv_bfloat16& l) {
    h = __float2bfloat16(v);
    l = __float2bfloat16(v - __bfloat162float(h));
}
__device__ __forceinline__ uint32_t pk(__nv_bfloat16 a, __nv_bfloat16 b) {
    __nv_bfloat162 t; t.x = a; t.y = b;
    return *reinterpret_cast<uint32_t*>(&t);
}

// ---------------- prep kernels ----------------
__global__ __launch_bounds__(256) void prep_x(const float* __restrict__ x) {
    size_t i = (size_t)blockIdx.x * 256 + threadIdx.x;  // float4 index
    const size_t total = (size_t)(NROWS + 1) * (HC / 4);
    if (i >= total) return;
    float4 v = make_float4(0.f, 0.f, 0.f, 0.f);
    if (i < (size_t)NROWS * (HC / 4)) v = reinterpret_cast<const float4*>(x)[i];
    __nv_bfloat16 h0, h1, h2, h3, l0, l1, l2, l3;
    split1(v.x, h0, l0); split1(v.y, h1, l1); split1(v.z, h2, l2); split1(v.w, h3, l3);
    reinterpret_cast<uint2*>(g_xh)[i] = make_uint2(pk(h0, h1), pk(h2, h3));
    reinterpret_cast<uint2*>(g_xl)[i] = make_uint2(pk(l0, l1), pk(l2, l3));
}

// Fragment mapping (derived from the validated ldmatrix path):
//   reg r element e of lane l = W[k][c][n],  c = ks*16 + (l&3)*2 + r*8 + e,
//   n = nt*8 + (l>>2).
__global__ __launch_bounds__(256) void prep_w(const float* __restrict__ Wa,
                                              const float* __restrict__ Wb) {
    int i = blockIdx.x * 256 + threadIdx.x;
    if (i >= 2 * WFRAG_PER_LAYER) return;
    const int L    = i / WFRAG_PER_LAYER;
    int rem        = i % WFRAG_PER_LAYER;
    const int k    = rem / 1024;  rem %= 1024;
    const int ks   = rem / 256;   rem %= 256;
    const int nt   = rem / 32;
    const int lane = rem % 32;
    const int n  = nt * 8 + (lane >> 2);
    const int c0 = ks * 16 + (lane & 3) * 2;
    const float* Wk = (L ? Wb : Wa) + (size_t)k * HC * HC;
    const float v00 = Wk[(c0 + 0) * HC + n], v01 = Wk[(c0 + 1) * HC + n];
    const float v10 = Wk[(c0 + 8) * HC + n], v11 = Wk[(c0 + 9) * HC + n];
    __nv_bfloat16 h00, l00, h01, l01, h10, l10, h11, l11;
    split1(v00, h00, l00); split1(v01, h01, l01);
    split1(v10, h10, l10); split1(v11, h11, l11);
    uint4 o;
    o.x = pk(h00, h01); o.y = pk(h10, h11);
    o.z = pk(l00, l01); o.w = pk(l10, l11);
    g_wf[i] = o;
}

// ---------------- main HMMA kernel ----------------
// Dynamic smem: nbr cache 13824B + per-warp double-buffered stages
// (4 warps x 2 stages x 8KB; each stage = hi 4K | lo 4K).
// Warp-private A + intra-warp software pipeline: while the MMA block for
// offset k runs, the gather for k+1 streams into the alternate stage in
// 4 chunk-slices (2 LDG pairs held in regs per slice = 16 regs peak).
#define NBR_BYTES (KOFF * TILE_M * 4)
#define A_LO 4096
#define WSTAGE 8192
#define SMEM_TOTAL (NBR_BYTES + 4 * 2 * WSTAGE)

template <bool FIRST>
__global__ __launch_bounds__(128, 2)
void spconv_hmma(const __nv_bfloat16* __restrict__ fh,
                 const __nv_bfloat16* __restrict__ fl,
                 const uint4* __restrict__ wf,
                 const int* __restrict__ nbr,
                 const float* __restrict__ x,
                 __nv_bfloat16* __restrict__ mh,
                 __nv_bfloat16* __restrict__ ml,
                 float* __restrict__ out)
{
    extern __shared__ __align__(128) char smx[];
    int* nbr_s = reinterpret_cast<int*>(smx);

    const int tid  = threadIdx.x;
    const int wid  = tid >> 5;
    const int lane = tid & 31;
    const int row0 = blockIdx.x * TILE_M;

    char* my_base = smx + NBR_BYTES + wid * (2 * WSTAGE);
    const uint32_t sbase_w = smem_u32(my_base);

    // ldmatrix A lane decomposition (x4 = 4 8x8 b16 matrices), warp-local rows
    const int lm = lane & 7, lg = lane >> 3;
    const int a_row   = (lg & 1) * 8 + lm;   // + t*16   (0..31 local)
    const int a_chunk = (lg >> 1);           // + ks*2

    // gather decomposition: 8 lanes per 128B row -> 4 rows per slice
    const int r4    = lane >> 3;   // 0..3
    const int chunk = lane & 7;    // 16B chunk within row

    // ---- warp-local nbr cache: this warp's 32 rows, all 27 offsets ----
    const int myrow = wid * 32;
    #pragma unroll 9
    for (int j = 0; j < KOFF; j++)
        nbr_s[j * TILE_M + myrow + lane] =
            nbr[(size_t)(row0 + myrow + lane) * KOFF + j];
    __syncwarp();

    float acc[2][8][4];
    #pragma unroll
    for (int t = 0; t < 2; t++)
        #pragma unroll
        for (int n = 0; n < 8; n++)
            #pragma unroll
            for (int j = 0; j < 4; j++) acc[t][n][j] = 0.f;

    // ---- prologue: direct fill of stage 0 with offset 0 ----
    {
        const int* nk = nbr_s + 0 * TILE_M + myrow;
        #pragma unroll
        for (int g = 0; g < 8; g++) {
            const int row = g * 4 + r4;
            const int nb  = nk[row];
            const uint4 vh = __ldg(reinterpret_cast<const uint4*>(
                                       fh + (size_t)nb * HC) + chunk);
            const uint4 vl = __ldg(reinterpret_cast<const uint4*>(
                                       fl + (size_t)nb * HC) + chunk);
            const uint32_t off = (uint32_t)row * 128 +
                                 (uint32_t)((chunk ^ (row & 7)) << 4);
            *reinterpret_cast<uint4*>(my_base + off)        = vh;
            *reinterpret_cast<uint4*>(my_base + A_LO + off) = vl;
        }
        __syncwarp();
    }

    for (int k = 0; k < KOFF; k++) {
        const int s = k & 1;
        const uint32_t tb = sbase_w + (uint32_t)s * WSTAGE;
        char* tnext = my_base + (s ^ 1) * WSTAGE;
        const int* nkn = nbr_s + (k + 1 < KOFF ? (k + 1) : k) * TILE_M + myrow;
        const bool pf = (k + 1 < KOFF);

        const uint4* wfk = wf + (size_t)k * (4 * 8 * 32);
        #pragma unroll
        for (int ks = 0; ks < 4; ks++) {
            // -- early LDG: 2 gather slices for offset k+1 (16 regs live) --
            uint4 pvh[2], pvl[2];
            int prow[2];
            if (pf) {
                #pragma unroll
                for (int j = 0; j < 2; j++) {
                    const int row = (ks * 2 + j) * 4 + r4;
                    prow[j] = row;
                    const int nb = nkn[row];
                    pvh[j] = __ldg(reinterpret_cast<const uint4*>(
                                       fh + (size_t)nb * HC) + chunk);
                    pvl[j] = __ldg(reinterpret_cast<const uint4*>(
                                       fl + (size_t)nb * HC) + chunk);
                }
            }

            // -- A fragments + 24 MMAs for this ks (covers the LDG latency) --
            uint32_t ah[2][4], al[2][4];
            #pragma unroll
            for (int t = 0; t < 2; t++) {
                const int rA = a_row + t * 16;
                const uint32_t cc = (uint32_t)(a_chunk + ks * 2);
                const uint32_t off = (uint32_t)rA * 128 + ((cc ^ (rA & 7)) << 4);
                ldm4(ah[t], tb + off);
                ldm4(al[t], tb + A_LO + off);
            }
            #pragma unroll
            for (int nt = 0; nt < 8; nt++) {
                const uint4 bf = __ldg(&wfk[(ks * 8 + nt) * 32 + lane]);
                const uint32_t bh[2] = {bf.x, bf.y};
                const uint32_t bl[2] = {bf.z, bf.w};
                #pragma unroll
                for (int t = 0; t < 2; t++) {
                    float* c = acc[t][nt];
                    mma16816(c, ah[t], bh);   // Ah*Bh
                    mma16816(c, ah[t], bl);   // Ah*Bl
                    mma16816(c, al[t], bh);   // Al*Bh
                }
            }

            // -- late STS: retire the 2 slices into the next stage --
            if (pf) {
                #pragma unroll
                for (int j = 0; j < 2; j++) {
                    const uint32_t off = (uint32_t)prow[j] * 128 +
                                         (uint32_t)((chunk ^ (prow[j] & 7)) << 4);
                    *reinterpret_cast<uint4*>(tnext + off)        = pvh[j];
                    *reinterpret_cast<uint4*>(tnext + A_LO + off) = pvl[j];
                }
            }
        }
        __syncwarp();   // cross-lane: STS of stage s^1 visible to next ldmatrix
    }

    // --- epilogue (register fragments -> global) ---
    const int erow = row0 + wid * 32 + (lane >> 2);
    const int ecol = (lane & 3) * 2;
    #pragma unroll
    for (int t = 0; t < 2; t++) {
        #pragma unroll
        for (int n = 0; n < 8; n++) {
            #pragma unroll
            for (int rr = 0; rr < 2; rr++) {
                const int r = erow + t * 16 + rr * 8;
                const int c = n * 8 + ecol;
                float v0 = acc[t][n][2 * rr];
                float v1 = acc[t][n][2 * rr + 1];
                if (FIRST) {
                    v0 = fmaxf(v0, 0.f);
                    v1 = fmaxf(v1, 0.f);
                    __nv_bfloat16 h0, l0, h1, l1;
                    split1(v0, h0, l0);
                    split1(v1, h1, l1);
                    *reinterpret_cast<uint32_t*>(mh + (size_t)r * HC + c) = pk(h0, h1);
                    *reinterpret_cast<uint32_t*>(ml + (size_t)r * HC + c) = pk(l0, l1);
                } else {
                    const float2 xv =
                        *reinterpret_cast<const float2*>(x + (size_t)r * HC + c);
                    float2 o;
                    o.x = v0 + xv.x;
                    o.y = v1 + xv.y;
                    *reinterpret_cast<float2*>(out + (size_t)r * HC + c) = o;
                }
            }
        }
    }
}

// ---------------- launch ----------------
extern "C" void kernel_launch(void* const* d_in, const int* in_sizes, int n_in,
                              void* d_out, int out_size) {
    const float* x   = (const float*)d_in[0];
    const float* Wa  = (const float*)d_in[1];
    const float* Wb  = (const float*)d_in[2];
    const int*   nbr = (const int*)d_in[3];
    float*       out = (float*)d_out;

    __nv_bfloat16 *xh, *xl, *mh, *ml;
    uint4* wfp;
    cudaGetSymbolAddress((void**)&xh, g_xh);
    cudaGetSymbolAddress((void**)&xl, g_xl);
    cudaGetSymbolAddress((void**)&mh, g_mh);
    cudaGetSymbolAddress((void**)&ml, g_ml);
    cudaGetSymbolAddress((void**)&wfp, g_wf);

    cudaFuncSetAttribute(spconv_hmma<true>,
                         cudaFuncAttributeMaxDynamicSharedMemorySize, SMEM_TOTAL);
    cudaFuncSetAttribute(spconv_hmma<false>,
                         cudaFuncAttributeMaxDynamicSharedMemorySize, SMEM_TOTAL);

    const size_t xtot = (size_t)(NROWS + 1) * (HC / 4);
    prep_x<<<(int)((xtot + 255) / 256), 256>>>(x);
    prep_w<<<(2 * WFRAG_PER_LAYER + 255) / 256, 256>>>(Wa, Wb);

    // layer 1: relu(conv(x, Wa)) -> split mid
    spconv_hmma<true><<<NBLK, 128, SMEM_TOTAL>>>(
        xh, xl, wfp, nbr, nullptr, mh, ml, nullptr);
    // layer 2: conv(mid, Wb) + x -> out
    spconv_hmma<false><<<NBLK, 128, SMEM_TOTAL>>>(
        mh, ml, wfp + WFRAG_PER_LAYER, nbr, x, nullptr, nullptr, out);
}

// round 14
// speedup vs baseline: 1.5529x; 1.5529x over previous
#include <cuda_runtime.h>
#include <cuda_fp16.h>
#include <cstdint>

#define NROWS 262144
#define HC 64
#define KOFF 27
#define TILE_M 128
#define NBLK (NROWS / TILE_M)

// weight fragments per layer: 27 k * 4 ks * 8 nt * 32 lanes uint4
#define WFRAG_PER_LAYER (KOFF * 4 * 8 * 32)

// ---------------- device scratch (no allocations allowed) ----------------
// Row NROWS is a zero sentinel (zero-initialized, never written) so gathers
// need no bounds check.
__device__ __align__(128) __half g_xf[(size_t)(NROWS + 8) * HC];  // fp16 x
__device__ __align__(128) __half g_mf[(size_t)(NROWS + 8) * HC];  // fp16 mid
// W in mma-B fragment order: uint4 = {bh_r0, bh_r1, bl_r0, bl_r1} (fp16 hi/lo)
__device__ uint4 g_wf[2 * WFRAG_PER_LAYER];

// ---------------- helpers (baseline PTX: ldmatrix / mma.sync) ------------
__device__ __forceinline__ uint32_t smem_u32(const void* p) {
    uint32_t a;
    asm("{ .reg .u64 t; cvta.to.shared.u64 t, %1; cvt.u32.u64 %0, t; }" : "=r"(a) : "l"(p));
    return a;
}
__device__ __forceinline__ void ldm4(uint32_t* r, uint32_t addr) {
    asm volatile("ldmatrix.sync.aligned.m8n8.x4.shared.b16 {%0,%1,%2,%3}, [%4];"
                 : "=r"(r[0]), "=r"(r[1]), "=r"(r[2]), "=r"(r[3]) : "r"(addr));
}
__device__ __forceinline__ void mma16816h(float* c, const uint32_t* a, const uint32_t* b) {
    asm volatile("mma.sync.aligned.m16n8k16.row.col.f32.f16.f16.f32 "
                 "{%0,%1,%2,%3}, {%4,%5,%6,%7}, {%8,%9}, {%0,%1,%2,%3};"
                 : "+f"(c[0]), "+f"(c[1]), "+f"(c[2]), "+f"(c[3])
                 : "r"(a[0]), "r"(a[1]), "r"(a[2]), "r"(a[3]), "r"(b[0]), "r"(b[1]));
}
__device__ __forceinline__ void splith(float v, __half& h, __half& l) {
    h = __float2half(v);
    l = __float2half(v - __half2float(h));
}
__device__ __forceinline__ uint32_t pkh(__half a, __half b) {
    __half2 t; t.x = a; t.y = b;
    return *reinterpret_cast<uint32_t*>(&t);
}

// ---------------- prep kernels ----------------
__global__ __launch_bounds__(256) void prep_x(const float* __restrict__ x) {
    size_t i = (size_t)blockIdx.x * 256 + threadIdx.x;  // float4 index
    const size_t total = (size_t)(NROWS + 1) * (HC / 4);
    if (i >= total) return;
    float4 v = make_float4(0.f, 0.f, 0.f, 0.f);
    if (i < (size_t)NROWS * (HC / 4)) v = reinterpret_cast<const float4*>(x)[i];
    reinterpret_cast<uint2*>(g_xf)[i] =
        make_uint2(pkh(__float2half(v.x), __float2half(v.y)),
                   pkh(__float2half(v.z), __float2half(v.w)));
}

// Fragment mapping (derived from the validated ldmatrix path):
//   reg r element e of lane l = W[k][c][n],  c = ks*16 + (l&3)*2 + r*8 + e,
//   n = nt*8 + (l>>2).
__global__ __launch_bounds__(256) void prep_w(const float* __restrict__ Wa,
                                              const float* __restrict__ Wb) {
    int i = blockIdx.x * 256 + threadIdx.x;
    if (i >= 2 * WFRAG_PER_LAYER) return;
    const int L    = i / WFRAG_PER_LAYER;
    int rem        = i % WFRAG_PER_LAYER;
    const int k    = rem / 1024;  rem %= 1024;
    const int ks   = rem / 256;   rem %= 256;
    const int nt   = rem / 32;
    const int lane = rem % 32;
    const int n  = nt * 8 + (lane >> 2);
    const int c0 = ks * 16 + (lane & 3) * 2;
    const float* Wk = (L ? Wb : Wa) + (size_t)k * HC * HC;
    const float v00 = Wk[(c0 + 0) * HC + n], v01 = Wk[(c0 + 1) * HC + n];
    const float v10 = Wk[(c0 + 8) * HC + n], v11 = Wk[(c0 + 9) * HC + n];
    __half h00, l00, h01, l01, h10, l10, h11, l11;
    splith(v00, h00, l00); splith(v01, h01, l01);
    splith(v10, h10, l10); splith(v11, h11, l11);
    uint4 o;
    o.x = pkh(h00, h01); o.y = pkh(h10, h11);
    o.z = pkh(l00, l01); o.w = pkh(l10, l11);
    g_wf[i] = o;
}

// ---------------- main HMMA kernel ----------------
// smem: A tile only (single fp16), XOR-swizzled 128B rows: 16KB static.
template <bool FIRST>
__global__ __launch_bounds__(128, 3)
void spconv_hmma(const __half* __restrict__ ff,
                 const uint4* __restrict__ wf,
                 const int* __restrict__ nbr,
                 const float* __restrict__ x,
                 __half* __restrict__ mf,
                 float* __restrict__ out)
{
    __shared__ __align__(128) char sm[16384];
    const uint32_t sbase = smem_u32(sm);
    const int tid  = threadIdx.x;
    const int wid  = tid >> 5;
    const int lane = tid & 31;
    const int row0 = blockIdx.x * TILE_M;

    // ldmatrix A lane decomposition (x4 = 4 8x8 b16 matrices)
    const int lm = lane & 7, lg = lane >> 3;
    const int a_row   = wid * 32 + (lg & 1) * 8 + lm;  // + t*16
    const int a_chunk = (lg >> 1);                     // + ks*2

    // coalesced gather decomposition: 8 lanes per 128B row
    const int rsub  = tid >> 3;   // 0..15
    const int chunk = tid & 7;    // 16B chunk within row

    float acc[2][8][4];
    #pragma unroll
    for (int t = 0; t < 2; t++)
        #pragma unroll
        for (int n = 0; n < 8; n++)
            #pragma unroll
            for (int j = 0; j < 4; j++) acc[t][n][j] = 0.f;

    for (int k = 0; k < KOFF; k++) {
        __syncthreads();   // previous iteration's readers done with the stage

        // ---- gather A (single fp16), coalesced: 8 lanes share one row ----
        #pragma unroll
        for (int g = 0; g < 8; g++) {
            const int row = g * 16 + rsub;
            const int nb  = __ldg(&nbr[(size_t)(row0 + row) * KOFF + k]);
            const uint4 v = __ldg(reinterpret_cast<const uint4*>(
                                      ff + (size_t)nb * HC) + chunk);
            const uint32_t off = (uint32_t)row * 128 +
                                 (uint32_t)((chunk ^ (row & 7)) << 4);
            *reinterpret_cast<uint4*>(sm + off) = v;
        }
        __syncthreads();

        // ---- 128x64x64 GEMM, 2 passes (A*Bh + A*Bl); B from gmem frags ----
        const uint4* wfk = wf + (size_t)k * (4 * 8 * 32);
        #pragma unroll
        for (int ks = 0; ks < 4; ks++) {
            uint32_t ah[2][4];
            #pragma unroll
            for (int t = 0; t < 2; t++) {
                const int rA = a_row + t * 16;
                const uint32_t cc = (uint32_t)(a_chunk + ks * 2);
                const uint32_t off = (uint32_t)rA * 128 + ((cc ^ (rA & 7)) << 4);
                ldm4(ah[t], sbase + off);
            }
            #pragma unroll
            for (int nt = 0; nt < 8; nt++) {
                const uint4 bf = __ldg(&wfk[(ks * 8 + nt) * 32 + lane]);
                const uint32_t bh[2] = {bf.x, bf.y};
                const uint32_t bl[2] = {bf.z, bf.w};
                #pragma unroll
                for (int t = 0; t < 2; t++) {
                    float* c = acc[t][nt];
                    mma16816h(c, ah[t], bh);   // A*Bh
                    mma16816h(c, ah[t], bl);   // A*Bl
                }
            }
        }
    }

    // --- epilogue (register fragments -> global) ---
    const int erow = row0 + wid * 32 + (lane >> 2);
    const int ecol = (lane & 3) * 2;
    #pragma unroll
    for (int t = 0; t < 2; t++) {
        #pragma unroll
        for (int n = 0; n < 8; n++) {
            #pragma unroll
            for (int rr = 0; rr < 2; rr++) {
                const int r = erow + t * 16 + rr * 8;
                const int c = n * 8 + ecol;
                float v0 = acc[t][n][2 * rr];
                float v1 = acc[t][n][2 * rr + 1];
                if (FIRST) {
                    v0 = fmaxf(v0, 0.f);
                    v1 = fmaxf(v1, 0.f);
                    *reinterpret_cast<uint32_t*>(mf + (size_t)r * HC + c) =
                        pkh(__float2half(v0), __float2half(v1));
                } else {
                    const float2 xv =
                        *reinterpret_cast<const float2*>(x + (size_t)r * HC + c);
                    float2 o;
                    o.x = v0 + xv.x;
                    o.y = v1 + xv.y;
                    *reinterpret_cast<float2*>(out + (size_t)r * HC + c) = o;
                }
            }
        }
    }
}

// ---------------- launch ----------------
extern "C" void kernel_launch(void* const* d_in, const int* in_sizes, int n_in,
                              void* d_out, int out_size) {
    const float* x   = (const float*)d_in[0];
    const float* Wa  = (const float*)d_in[1];
    const float* Wb  = (const float*)d_in[2];
    const int*   nbr = (const int*)d_in[3];
    float*       out = (float*)d_out;

    __half *xf, *mf;
    uint4* wfp;
    cudaGetSymbolAddress((void**)&xf, g_xf);
    cudaGetSymbolAddress((void**)&mf, g_mf);
    cudaGetSymbolAddress((void**)&wfp, g_wf);

    const size_t xtot = (size_t)(NROWS + 1) * (HC / 4);
    prep_x<<<(int)((xtot + 255) / 256), 256>>>(x);
    prep_w<<<(2 * WFRAG_PER_LAYER + 255) / 256, 256>>>(Wa, Wb);

    // layer 1: relu(conv(x, Wa)) -> fp16 mid
    spconv_hmma<true><<<NBLK, 128>>>(xf, wfp, nbr, nullptr, mf, nullptr);
    // layer 2: conv(mid, Wb) + x -> out
    spconv_hmma<false><<<NBLK, 128>>>(mf, wfp + WFRAG_PER_LAYER, nbr, x,
                                      nullptr, out);
}

// round 15
// speedup vs baseline: 1.5817x; 1.0185x over previous
#include <cuda_runtime.h>
#include <cuda_fp16.h>
#include <cstdint>

#define NROWS 262144
#define HC 64
#define KOFF 27
#define TILE_M 128
#define NBLK (NROWS / TILE_M)

// weight fragments per layer: 27 k * 4 ks * 8 nt * 32 lanes uint2 (fp16)
#define WFRAG_PER_LAYER (KOFF * 4 * 8 * 32)

// ---------------- device scratch (no allocations allowed) ----------------
// Row NROWS is a zero sentinel (zero-initialized, never written) so gathers
// need no bounds check.
__device__ __align__(128) __half g_xf[(size_t)(NROWS + 8) * HC];  // fp16 x
__device__ __align__(128) __half g_mf[(size_t)(NROWS + 8) * HC];  // fp16 mid
// W in mma-B fragment order: uint2 = {b_r0, b_r1} (fp16, single precision pass)
__device__ uint2 g_wf[2 * WFRAG_PER_LAYER];

// ---------------- helpers (baseline PTX: ldmatrix / mma.sync) ------------
__device__ __forceinline__ uint32_t smem_u32(const void* p) {
    uint32_t a;
    asm("{ .reg .u64 t; cvta.to.shared.u64 t, %1; cvt.u32.u64 %0, t; }" : "=r"(a) : "l"(p));
    return a;
}
__device__ __forceinline__ void ldm4(uint32_t* r, uint32_t addr) {
    asm volatile("ldmatrix.sync.aligned.m8n8.x4.shared.b16 {%0,%1,%2,%3}, [%4];"
                 : "=r"(r[0]), "=r"(r[1]), "=r"(r[2]), "=r"(r[3]) : "r"(addr));
}
__device__ __forceinline__ void mma16816h(float* c, const uint32_t* a, const uint32_t* b) {
    asm volatile("mma.sync.aligned.m16n8k16.row.col.f32.f16.f16.f32 "
                 "{%0,%1,%2,%3}, {%4,%5,%6,%7}, {%8,%9}, {%0,%1,%2,%3};"
                 : "+f"(c[0]), "+f"(c[1]), "+f"(c[2]), "+f"(c[3])
                 : "r"(a[0]), "r"(a[1]), "r"(a[2]), "r"(a[3]), "r"(b[0]), "r"(b[1]));
}
__device__ __forceinline__ uint32_t pkh(__half a, __half b) {
    __half2 t; t.x = a; t.y = b;
    return *reinterpret_cast<uint32_t*>(&t);
}

// ---------------- prep kernels ----------------
__global__ __launch_bounds__(256) void prep_x(const float* __restrict__ x) {
    size_t i = (size_t)blockIdx.x * 256 + threadIdx.x;  // float4 index
    const size_t total = (size_t)(NROWS + 1) * (HC / 4);
    if (i >= total) return;
    float4 v = make_float4(0.f, 0.f, 0.f, 0.f);
    if (i < (size_t)NROWS * (HC / 4)) v = reinterpret_cast<const float4*>(x)[i];
    reinterpret_cast<uint2*>(g_xf)[i] =
        make_uint2(pkh(__float2half(v.x), __float2half(v.y)),
                   pkh(__float2half(v.z), __float2half(v.w)));
}

// Fragment mapping (derived from the validated ldmatrix path):
//   reg r element e of lane l = W[k][c][n],  c = ks*16 + (l&3)*2 + r*8 + e,
//   n = nt*8 + (l>>2).
__global__ __launch_bounds__(256) void prep_w(const float* __restrict__ Wa,
                                              const float* __restrict__ Wb) {
    int i = blockIdx.x * 256 + threadIdx.x;
    if (i >= 2 * WFRAG_PER_LAYER) return;
    const int L    = i / WFRAG_PER_LAYER;
    int rem        = i % WFRAG_PER_LAYER;
    const int k    = rem / 1024;  rem %= 1024;
    const int ks   = rem / 256;   rem %= 256;
    const int nt   = rem / 32;
    const int lane = rem % 32;
    const int n  = nt * 8 + (lane >> 2);
    const int c0 = ks * 16 + (lane & 3) * 2;
    const float* Wk = (L ? Wb : Wa) + (size_t)k * HC * HC;
    uint2 o;
    o.x = pkh(__float2half(Wk[(c0 + 0) * HC + n]),
              __float2half(Wk[(c0 + 1) * HC + n]));
    o.y = pkh(__float2half(Wk[(c0 + 8) * HC + n]),
              __float2half(Wk[(c0 + 9) * HC + n]));
    g_wf[i] = o;
}

// ---------------- main HMMA kernel ----------------
// Static smem: nbr cache (13.5KB) + A tile (16KB, XOR-swizzled 128B rows).
template <bool FIRST>
__global__ __launch_bounds__(128, 3)
void spconv_hmma(const __half* __restrict__ ff,
                 const uint2* __restrict__ wf,
                 const int* __restrict__ nbr,
                 const float* __restrict__ x,
                 __half* __restrict__ mf,
                 float* __restrict__ out)
{
    __shared__ __align__(128) int  nbr_s[KOFF * TILE_M];
    __shared__ __align__(128) char sm[16384];
    const uint32_t sbase = smem_u32(sm);
    const int tid  = threadIdx.x;
    const int wid  = tid >> 5;
    const int lane = tid & 31;
    const int row0 = blockIdx.x * TILE_M;

    // ldmatrix A lane decomposition (x4 = 4 8x8 b16 matrices)
    const int lm = lane & 7, lg = lane >> 3;
    const int a_row   = wid * 32 + (lg & 1) * 8 + lm;  // + t*16
    const int a_chunk = (lg >> 1);                     // + ks*2

    // coalesced gather decomposition: 8 lanes per 128B row
    const int rsub  = tid >> 3;   // 0..15
    const int chunk = tid & 7;    // 16B chunk within row

    // ---- cache all neighbor indices for this block (one-time) ----
    #pragma unroll 9
    for (int j = 0; j < KOFF; j++)
        nbr_s[j * TILE_M + tid] = nbr[(size_t)(row0 + tid) * KOFF + j];

    float acc[2][8][4];
    #pragma unroll
    for (int t = 0; t < 2; t++)
        #pragma unroll
        for (int n = 0; n < 8; n++)
            #pragma unroll
            for (int j = 0; j < 4; j++) acc[t][n][j] = 0.f;

    __syncthreads();   // nbr cache ready

    for (int k = 0; k < KOFF; k++) {
        // ---- gather A (fp16), coalesced: 8 lanes share one 128B row ----
        const int* nk = nbr_s + k * TILE_M;
        #pragma unroll
        for (int g = 0; g < 8; g++) {
            const int row = g * 16 + rsub;
            const int nb  = nk[row];
            const uint4 v = __ldg(reinterpret_cast<const uint4*>(
                                      ff + (size_t)nb * HC) + chunk);
            const uint32_t off = (uint32_t)row * 128 +
                                 (uint32_t)((chunk ^ (row & 7)) << 4);
            *reinterpret_cast<uint4*>(sm + off) = v;
        }
        __syncthreads();

        // ---- 128x64x64 GEMM, single fp16 pass; B from gmem frags ----
        const uint2* wfk = wf + (size_t)k * (4 * 8 * 32);
        #pragma unroll
        for (int ks = 0; ks < 4; ks++) {
            uint32_t ah[2][4];
            #pragma unroll
            for (int t = 0; t < 2; t++) {
                const int rA = a_row + t * 16;
                const uint32_t cc = (uint32_t)(a_chunk + ks * 2);
                const uint32_t off = (uint32_t)rA * 128 + ((cc ^ (rA & 7)) << 4);
                ldm4(ah[t], sbase + off);
            }
            #pragma unroll
            for (int nt = 0; nt < 8; nt++) {
                const uint2 bf = __ldg(&wfk[(ks * 8 + nt) * 32 + lane]);
                const uint32_t bb[2] = {bf.x, bf.y};
                #pragma unroll
                for (int t = 0; t < 2; t++)
                    mma16816h(acc[t][nt], ah[t], bb);
            }
        }
        __syncthreads();   // all warps done reading before next overwrite
    }

    // --- epilogue (register fragments -> global) ---
    const int erow = row0 + wid * 32 + (lane >> 2);
    const int ecol = (lane & 3) * 2;
    #pragma unroll
    for (int t = 0; t < 2; t++) {
        #pragma unroll
        for (int n = 0; n < 8; n++) {
            #pragma unroll
            for (int rr = 0; rr < 2; rr++) {
                const int r = erow + t * 16 + rr * 8;
                const int c = n * 8 + ecol;
                float v0 = acc[t][n][2 * rr];
                float v1 = acc[t][n][2 * rr + 1];
                if (FIRST) {
                    v0 = fmaxf(v0, 0.f);
                    v1 = fmaxf(v1, 0.f);
                    *reinterpret_cast<uint32_t*>(mf + (size_t)r * HC + c) =
                        pkh(__float2half(v0), __float2half(v1));
                } else {
                    const float2 xv =
                        *reinterpret_cast<const float2*>(x + (size_t)r * HC + c);
                    float2 o;
                    o.x = v0 + xv.x;
                    o.y = v1 + xv.y;
                    *reinterpret_cast<float2*>(out + (size_t)r * HC + c) = o;
                }
            }
        }
    }
}

// ---------------- launch ----------------
extern "C" void kernel_launch(void* const* d_in, const int* in_sizes, int n_in,
                              void* d_out, int out_size) {
    const float* x   = (const float*)d_in[0];
    const float* Wa  = (const float*)d_in[1];
    const float* Wb  = (const float*)d_in[2];
    const int*   nbr = (const int*)d_in[3];
    float*       out = (float*)d_out;

    __half *xf, *mf;
    uint2* wfp;
    cudaGetSymbolAddress((void**)&xf, g_xf);
    cudaGetSymbolAddress((void**)&mf, g_mf);
    cudaGetSymbolAddress((void**)&wfp, g_wf);

    const size_t xtot = (size_t)(NROWS + 1) * (HC / 4);
    prep_x<<<(int)((xtot + 255) / 256), 256>>>(x);
    prep_w<<<(2 * WFRAG_PER_LAYER + 255) / 256, 256>>>(Wa, Wb);

    // layer 1: relu(conv(x, Wa)) -> fp16 mid
    spconv_hmma<true><<<NBLK, 128>>>(xf, wfp, nbr, nullptr, mf, nullptr);
    // layer 2: conv(mid, Wb) + x -> out
    spconv_hmma<false><<<NBLK, 128>>>(mf, wfp + WFRAG_PER_LAYER, nbr, x,
                                      nullptr, out);
}